// round 2
// baseline (speedup 1.0000x reference)
#include <cuda_runtime.h>

// CormorantCGProduct: full CG tensor product for LMAX=3, N=1024, TAU=16.
// Input order (metadata/dict insertion order!): A0,B0,A1,B1,A2,B2,A3,B3,
// each (2, N, 2l+1, 16) fp32.
// Output: concat over l=0..3 of (2, N, 2l+1, 256*npairs_l) fp32.

#define NTASKS 34
#define CGSTRIDE 343   // 7*7*7 dense (x,y,z) slab per (l1,l2,l) triple

// CG table computed on device each launch (deterministic, capture-safe).
__device__ float g_cg[NTASKS * CGSTRIDE];

// Task tables: for each task t, (l1, l2, l_out, pair channel offset).
// For each output l, pairs in (l1,l2) lexicographic order (matches the
// reference loop nest l1-outer, l2-inner appending to parts[l]).
__constant__ signed char c_l1[NTASKS] = {
    0,1,2,3,
    0,1,1,1,2,2,2,3,3,
    0,1,1,1,2,2,2,2,3,3,3,
    0,1,1,2,2,2,3,3,3,3};
__constant__ signed char c_l2[NTASKS] = {
    0,1,2,3,
    1,0,1,2,1,2,3,2,3,
    2,1,2,3,0,1,2,3,1,2,3,
    3,2,3,1,2,3,0,1,2,3};
__constant__ signed char c_lo[NTASKS] = {
    0,0,0,0,
    1,1,1,1,1,1,1,1,1,
    2,2,2,2,2,2,2,2,2,2,2,
    3,3,3,3,3,3,3,3,3,3};
__constant__ short c_poff[NTASKS] = {
    0,256,512,768,
    0,256,512,768,1024,1280,1536,1792,2048,
    0,256,512,768,1024,1280,1536,1792,2048,2304,2560,
    0,256,512,768,1024,1280,1536,1792,2048,2304};

// Channel width of each output degree: 256 * npairs_l
__constant__ int c_Cl[4] = {1024, 2304, 2816, 2560};

__device__ __forceinline__ double dfact(int n) {
    const double f[11] = {1.,1.,2.,6.,24.,120.,720.,5040.,40320.,362880.,3628800.};
    return f[n];
}

// ---------------------------------------------------------------------------
// Init kernel: fill g_cg with Clebsch-Gordan coefficients (Condon-Shortley),
// exactly matching the reference python formula, computed in double.
// ---------------------------------------------------------------------------
__global__ void cg_init_kernel() {
    int t   = blockIdx.x;
    int idx = threadIdx.x;
    if (idx >= CGSTRIDE) return;

    int l1 = c_l1[t], l2 = c_l2[t], l = c_lo[t];
    int x = idx / 49;
    int y = (idx / 7) % 7;
    int z = idx % 7;

    float val = 0.0f;
    if (x <= 2 * l1 && y <= 2 * l2 && z <= 2 * l) {
        int m1 = x - l1, m2 = y - l2, m = z - l;
        if (m1 + m2 == m) {
            double pref = (2.0 * l + 1.0)
                * dfact(l + l1 - l2) * dfact(l - l1 + l2) * dfact(l1 + l2 - l)
                / dfact(l1 + l2 + l + 1)
                * dfact(l + m) * dfact(l - m)
                * dfact(l1 - m1) * dfact(l1 + m1)
                * dfact(l2 - m2) * dfact(l2 + m2);
            pref = sqrt(pref);
            int kmin = max(0, max(l2 - l - m1, l1 - l + m2));
            int kmax = min(l1 + l2 - l, min(l1 - m1, l2 + m2));
            double s = 0.0;
            for (int k = kmin; k <= kmax; ++k) {
                double den = dfact(k) * dfact(l1 + l2 - l - k)
                           * dfact(l1 - m1 - k) * dfact(l2 + m2 - k)
                           * dfact(l - l2 + m1 + k) * dfact(l - l1 - m2 + k);
                double term = 1.0 / den;
                if (k & 1) term = -term;
                s += term;
            }
            val = (float)(pref * s);
        }
    }
    g_cg[t * CGSTRIDE + idx] = val;
}

// ---------------------------------------------------------------------------
// Main kernel: one block = one (task, n). 256 threads, thread = (c,d) pair.
// Writes 2*(2l+1) fully-coalesced 1KB rows per block with streaming stores.
// ---------------------------------------------------------------------------
__global__ void __launch_bounds__(256)
cgprod_kernel(const float* __restrict__ A0, const float* __restrict__ A1,
              const float* __restrict__ A2, const float* __restrict__ A3,
              const float* __restrict__ B0, const float* __restrict__ B1,
              const float* __restrict__ B2, const float* __restrict__ B3,
              float* __restrict__ out, int N) {
    __shared__ float sAr[7 * 16], sAi[7 * 16];
    __shared__ float sBr[7 * 16], sBi[7 * 16];
    __shared__ float sC[CGSTRIDE];

    const int t   = blockIdx.x;
    const int n   = blockIdx.y;
    const int tid = threadIdx.x;

    const int l1 = c_l1[t], l2 = c_l2[t], lo = c_lo[t];
    const int d1 = 2 * l1 + 1, d2 = 2 * l2 + 1, dz = 2 * lo + 1;

    const float* Aptr = (l1 == 0) ? A0 : (l1 == 1) ? A1 : (l1 == 2) ? A2 : A3;
    const float* Bptr = (l2 == 0) ? B0 : (l2 == 1) ? B1 : (l2 == 2) ? B2 : B3;

    // Stage A slice for this n: 2 * d1 * 16 <= 224 floats.
    {
        int nA = 2 * d1 * 16;
        if (tid < nA) {
            int s = tid / (d1 * 16);
            int r = tid - s * (d1 * 16);
            float v = Aptr[((long)(s * N + n) * d1) * 16 + r];
            if (s == 0) sAr[r] = v; else sAi[r] = v;
        }
        int nB = 2 * d2 * 16;
        if (tid < nB) {
            int s = tid / (d2 * 16);
            int r = tid - s * (d2 * 16);
            float v = Bptr[((long)(s * N + n) * d2) * 16 + r];
            if (s == 0) sBr[r] = v; else sBi[r] = v;
        }
    }
    // Stage CG slab for this task.
    for (int i = tid; i < CGSTRIDE; i += 256) sC[i] = g_cg[t * CGSTRIDE + i];
    __syncthreads();

    const int c = tid >> 4;
    const int d = tid & 15;

    // A row into registers (compile-time indices via full unroll).
    float ar[7], ai[7];
#pragma unroll
    for (int x = 0; x < 7; ++x) {
        ar[x] = (x < d1) ? sAr[x * 16 + c] : 0.0f;
        ai[x] = (x < d1) ? sAi[x * 16 + c] : 0.0f;
    }

    // Output base for degree lo (layout: concat of the four degree arrays).
    long b1 = 2L * N * 1 * 1024;
    long b2 = b1 + 2L * N * 3 * 2304;
    long b3 = b2 + 2L * N * 5 * 2816;
    long base = (lo == 0) ? 0L : (lo == 1) ? b1 : (lo == 2) ? b2 : b3;
    const int Cl   = c_Cl[lo];
    const int poff = c_poff[t];
    const int shift = l1 + l2 - lo;   // y = z + shift - x

    for (int z = 0; z < dz; ++z) {
        float accR = 0.0f, accI = 0.0f;
#pragma unroll
        for (int x = 0; x < 7; ++x) {
            if (x < d1) {
                int y = z + shift - x;
                if (y >= 0 && y < d2) {
                    float Cv  = sC[(x * 7 + y) * 7 + z];
                    float bry = sBr[y * 16 + d];
                    float biy = sBi[y * 16 + d];
                    accR = fmaf(Cv, fmaf(ar[x], bry, -ai[x] * biy), accR);
                    accI = fmaf(Cv, fmaf(ar[x], biy,  ai[x] * bry), accI);
                }
            }
        }
        long oR = base + ((long)(0 * N + n) * dz + z) * Cl + poff + tid;
        long oI = base + ((long)(1 * N + n) * dz + z) * Cl + poff + tid;
        __stcs(out + oR, accR);
        __stcs(out + oI, accI);
    }
}

// ---------------------------------------------------------------------------
extern "C" void kernel_launch(void* const* d_in, const int* in_sizes, int n_in,
                              void* d_out, int out_size) {
    // Dict insertion order in setup_inputs(): A0,B0,A1,B1,A2,B2,A3,B3
    const float* A0 = (const float*)d_in[0];
    const float* B0 = (const float*)d_in[1];
    const float* A1 = (const float*)d_in[2];
    const float* B1 = (const float*)d_in[3];
    const float* A2 = (const float*)d_in[4];
    const float* B2 = (const float*)d_in[5];
    const float* A3 = (const float*)d_in[6];
    const float* B3 = (const float*)d_in[7];
    float* out = (float*)d_out;

    int N = in_sizes[0] / (2 * 1 * 16);   // A0 is (2, N, 1, 16)

    cg_init_kernel<<<NTASKS, CGSTRIDE>>>();

    dim3 grid(NTASKS, N);
    cgprod_kernel<<<grid, 256>>>(A0, A1, A2, A3, B0, B1, B2, B3, out, N);
}

// round 3
// speedup vs baseline: 2.0618x; 2.0618x over previous
#include <cuda_runtime.h>

// CormorantCGProduct: full CG tensor product for LMAX=3, N=1024, TAU=16.
// Input order (dict insertion order): A0,B0,A1,B1,A2,B2,A3,B3,
// each (2, N, 2l+1, 16) fp32.
// Output: concat over l=0..3 of (2, N, 2l+1, 256*npairs_l) fp32.

#define NTASKS 34
#define CGSTRIDE 343   // 7*7*7 dense (x,y,z) slab per (l1,l2,l) triple

typedef unsigned long long ull;

// CG table computed on device each launch (deterministic, capture-safe).
__device__ float g_cg[NTASKS * CGSTRIDE];

__constant__ signed char c_l1[NTASKS] = {
    0,1,2,3,
    0,1,1,1,2,2,2,3,3,
    0,1,1,1,2,2,2,2,3,3,3,
    0,1,1,2,2,2,3,3,3,3};
__constant__ signed char c_l2[NTASKS] = {
    0,1,2,3,
    1,0,1,2,1,2,3,2,3,
    2,1,2,3,0,1,2,3,1,2,3,
    3,2,3,1,2,3,0,1,2,3};
__constant__ signed char c_lo[NTASKS] = {
    0,0,0,0,
    1,1,1,1,1,1,1,1,1,
    2,2,2,2,2,2,2,2,2,2,2,
    3,3,3,3,3,3,3,3,3,3};
__constant__ short c_poff[NTASKS] = {
    0,256,512,768,
    0,256,512,768,1024,1280,1536,1792,2048,
    0,256,512,768,1024,1280,1536,1792,2048,2304,2560,
    0,256,512,768,1024,1280,1536,1792,2048,2304};

__constant__ int c_Cl[4] = {1024, 2304, 2816, 2560};

__device__ __forceinline__ double dfact(int n) {
    const double f[11] = {1.,1.,2.,6.,24.,120.,720.,5040.,40320.,362880.,3628800.};
    return f[n];
}

// ---------------------------------------------------------------------------
// CG coefficient init (Condon-Shortley), exact match to reference formula.
// ---------------------------------------------------------------------------
__global__ void cg_init_kernel() {
    int t   = blockIdx.x;
    int idx = threadIdx.x;
    if (idx >= CGSTRIDE) return;

    int l1 = c_l1[t], l2 = c_l2[t], l = c_lo[t];
    int x = idx / 49;
    int y = (idx / 7) % 7;
    int z = idx % 7;

    float val = 0.0f;
    if (x <= 2 * l1 && y <= 2 * l2 && z <= 2 * l) {
        int m1 = x - l1, m2 = y - l2, m = z - l;
        if (m1 + m2 == m) {
            double pref = (2.0 * l + 1.0)
                * dfact(l + l1 - l2) * dfact(l - l1 + l2) * dfact(l1 + l2 - l)
                / dfact(l1 + l2 + l + 1)
                * dfact(l + m) * dfact(l - m)
                * dfact(l1 - m1) * dfact(l1 + m1)
                * dfact(l2 - m2) * dfact(l2 + m2);
            pref = sqrt(pref);
            int kmin = max(0, max(l2 - l - m1, l1 - l + m2));
            int kmax = min(l1 + l2 - l, min(l1 - m1, l2 + m2));
            double s = 0.0;
            for (int k = kmin; k <= kmax; ++k) {
                double den = dfact(k) * dfact(l1 + l2 - l - k)
                           * dfact(l1 - m1 - k) * dfact(l2 + m2 - k)
                           * dfact(l - l2 + m1 + k) * dfact(l - l1 - m2 + k);
                double term = 1.0 / den;
                if (k & 1) term = -term;
                s += term;
            }
            val = (float)(pref * s);
        }
    }
    g_cg[t * CGSTRIDE + idx] = val;
}

// ---- packed f32x2 helpers (Blackwell dual-rate fp32; PTX-only) ----------
__device__ __forceinline__ ull pack2(float lo, float hi) {
    ull r;
    asm("mov.b64 %0, {%1, %2};" : "=l"(r) : "f"(lo), "f"(hi));
    return r;
}
__device__ __forceinline__ void fma2(ull& d, ull a, ull b) {
    asm("fma.rn.f32x2 %0, %1, %2, %0;" : "+l"(d) : "l"(a), "l"(b));
}
__device__ __forceinline__ float2 unpack2(ull v) {
    float2 r;
    asm("mov.b64 {%0, %1}, %2;" : "=f"(r.x), "=f"(r.y) : "l"(v));
    return r;
}

// ---------------------------------------------------------------------------
// Main kernel: block = (task, 4 n-rows). 256 threads:
//   nn = tid>>6 (which n), lane = tid&63, c = lane>>2, d-group = (lane&3)*4.
// Thread computes 4 consecutive B-channels -> LDS.128 B reads, packed-f32x2
// FMAs, STG.128 streaming stores (2 per z-row).
// ---------------------------------------------------------------------------
__global__ void __launch_bounds__(256)
cgprod_kernel(const float* __restrict__ A0, const float* __restrict__ A1,
              const float* __restrict__ A2, const float* __restrict__ A3,
              const float* __restrict__ B0, const float* __restrict__ B1,
              const float* __restrict__ B2, const float* __restrict__ B3,
              float* __restrict__ out, int N) {
    __shared__ __align__(16) float sAr[4][112], sAi[4][112];
    __shared__ __align__(16) float sBr[4][112], sBi[4][112];
    __shared__ float sC[CGSTRIDE];

    const int t   = blockIdx.x;
    const int n0  = blockIdx.y * 4;
    const int tid = threadIdx.x;

    const int l1 = c_l1[t], l2 = c_l2[t], lo = c_lo[t];
    const int d1 = 2 * l1 + 1, d2 = 2 * l2 + 1, dz = 2 * lo + 1;

    const float* Aptr = (l1 == 0) ? A0 : (l1 == 1) ? A1 : (l1 == 2) ? A2 : A3;
    const float* Bptr = (l2 == 0) ? B0 : (l2 == 1) ? B1 : (l2 == 2) ? B2 : B3;

    // ---- stage A/B slices for 4 n rows ----
    {
        const int perA = d1 * 16;
        const int totA = 8 * perA;          // 4n * 2(s) * d1*16
        for (int i = tid; i < totA; i += 256) {
            int q = i / perA;               // 0..7 : (nn,s)
            int r = i - q * perA;           // x*16 + c
            int nn = q >> 1, s = q & 1;
            float v = Aptr[((long)(s * N + n0 + nn)) * perA + r];
            if (s == 0) sAr[nn][r] = v; else sAi[nn][r] = v;
        }
        const int perB = d2 * 16;
        const int totB = 8 * perB;
        for (int i = tid; i < totB; i += 256) {
            int q = i / perB;
            int r = i - q * perB;
            int nn = q >> 1, s = q & 1;
            float v = Bptr[((long)(s * N + n0 + nn)) * perB + r];
            if (s == 0) sBr[nn][r] = v; else sBi[nn][r] = v;
        }
    }
    for (int i = tid; i < CGSTRIDE; i += 256) sC[i] = g_cg[t * CGSTRIDE + i];
    __syncthreads();

    const int nn   = tid >> 6;
    const int lane = tid & 63;
    const int c    = lane >> 2;
    const int d4   = (lane & 3) * 4;
    const int n    = n0 + nn;

    // A row into registers.
    float ar[7], ai[7];
#pragma unroll
    for (int x = 0; x < 7; ++x) {
        ar[x] = (x < d1) ? sAr[nn][x * 16 + c] : 0.0f;
        ai[x] = (x < d1) ? sAi[nn][x * 16 + c] : 0.0f;
    }

    const float* sBrN = sBr[nn];
    const float* sBiN = sBi[nn];

    long b1 = 2L * N * 1 * 1024;
    long b2 = b1 + 2L * N * 3 * 2304;
    long b3 = b2 + 2L * N * 5 * 2816;
    long base = (lo == 0) ? 0L : (lo == 1) ? b1 : (lo == 2) ? b2 : b3;
    const int Cl    = c_Cl[lo];
    const int shift = l1 + l2 - lo;   // y = z + shift - x

    long offR = base + (long)n * dz * Cl + c_poff[t] + c * 16 + d4;
    long offI = offR + (long)N * dz * Cl;

    for (int z = 0; z < dz; ++z) {
        ull aR0 = 0, aR1 = 0, aI0 = 0, aI1 = 0;
#pragma unroll
        for (int x = 0; x < 7; ++x) {
            if (x < d1) {
                int y = z + shift - x;
                if ((unsigned)y < (unsigned)d2) {
                    float Cv  = sC[(x * 7 + y) * 7 + z];   // broadcast LDS
                    float car = Cv * ar[x];
                    float cai = Cv * ai[x];
                    ull car2 = pack2(car,  car);
                    ull caip = pack2(cai,  cai);
                    ull cain = pack2(-cai, -cai);
                    ulonglong2 br = *(const ulonglong2*)(sBrN + y * 16 + d4);
                    ulonglong2 bi = *(const ulonglong2*)(sBiN + y * 16 + d4);
                    fma2(aR0, car2, br.x);  fma2(aR0, cain, bi.x);
                    fma2(aR1, car2, br.y);  fma2(aR1, cain, bi.y);
                    fma2(aI0, car2, bi.x);  fma2(aI0, caip, br.x);
                    fma2(aI1, car2, bi.y);  fma2(aI1, caip, br.y);
                }
            }
        }
        float2 r0 = unpack2(aR0), r1 = unpack2(aR1);
        float2 i0 = unpack2(aI0), i1 = unpack2(aI1);
        __stcs((float4*)(out + offR), make_float4(r0.x, r0.y, r1.x, r1.y));
        __stcs((float4*)(out + offI), make_float4(i0.x, i0.y, i1.x, i1.y));
        offR += Cl;
        offI += Cl;
    }
}

// ---------------------------------------------------------------------------
extern "C" void kernel_launch(void* const* d_in, const int* in_sizes, int n_in,
                              void* d_out, int out_size) {
    // Dict insertion order in setup_inputs(): A0,B0,A1,B1,A2,B2,A3,B3
    const float* A0 = (const float*)d_in[0];
    const float* B0 = (const float*)d_in[1];
    const float* A1 = (const float*)d_in[2];
    const float* B1 = (const float*)d_in[3];
    const float* A2 = (const float*)d_in[4];
    const float* B2 = (const float*)d_in[5];
    const float* A3 = (const float*)d_in[6];
    const float* B3 = (const float*)d_in[7];
    float* out = (float*)d_out;

    int N = in_sizes[0] / (2 * 1 * 16);   // A0 is (2, N, 1, 16)

    cg_init_kernel<<<NTASKS, CGSTRIDE>>>();

    dim3 grid(NTASKS, N / 4);
    cgprod_kernel<<<grid, 256>>>(A0, A1, A2, A3, B0, B1, B2, B3, out, N);
}